// round 1
// baseline (speedup 1.0000x reference)
#include <cuda_runtime.h>
#include <math.h>

#define NROWS_DEF 131072
#define SDIM 64
#define HDIM 128
#define KC   512
#define ADIM 8
#define TM   64
#define NT   256

// Per-codebook precomputed head outputs + norms (scratch; no allocation allowed)
__device__ float g_probs[KC * ADIM];
__device__ float g_value[KC];
__device__ float g_enorm[KC];

// ---------------------------------------------------------------------------
// Kernel 0: per-codebook-entry head precompute.
// quantize == embedding[idx] exactly (straight-through), so softmax(E@Wa+ba)
// and E@Wv+bv can be computed once for all 512 codes.
// ---------------------------------------------------------------------------
__global__ void head_kernel(const float* __restrict__ E,
                            const float* __restrict__ Wa,
                            const float* __restrict__ ba,
                            const float* __restrict__ Wv,
                            const float* __restrict__ bv) {
    int c = blockIdx.x * blockDim.x + threadIdx.x;
    if (c >= KC) return;
    float logit[ADIM];
#pragma unroll
    for (int a = 0; a < ADIM; a++) logit[a] = ba[a];
    float en = 0.f, val = bv[0];
    for (int k = 0; k < HDIM; k++) {
        float ev = E[c * HDIM + k];
        en  = fmaf(ev, ev, en);
        val = fmaf(ev, Wv[k], val);
#pragma unroll
        for (int a = 0; a < ADIM; a++)
            logit[a] = fmaf(ev, Wa[k * ADIM + a], logit[a]);
    }
    float m = logit[0];
#pragma unroll
    for (int a = 1; a < ADIM; a++) m = fmaxf(m, logit[a]);
    float s = 0.f;
#pragma unroll
    for (int a = 0; a < ADIM; a++) { logit[a] = expf(logit[a] - m); s += logit[a]; }
    float inv = 1.f / s;
#pragma unroll
    for (int a = 0; a < ADIM; a++) g_probs[c * ADIM + a] = logit[a] * inv;
    g_value[c] = val;
    g_enorm[c] = en;
}

// ---------------------------------------------------------------------------
// Main fused kernel: 64 rows per block.
//   Phase 1: h = relu(in @ W1 + b1)      [64,64]@[64,128]
//   Phase 2: x = relu(h @ Wh + bh)       [64,128]@[128,128]
//   Phase 3: argmin_k (||e_k||^2 - 2 x.e_k) over 512 codes (2 tiles of 256)
//   Output:  gather precomputed probs/value by winning index.
// Shared memory (dynamic, 164,608 B):
//   s_h  [64][129]  (pad 129: odd stride -> conflict-free row access)
//   overlay region:
//     phases 1/2: s_in [64][65] then s_w [128][128]
//     phase 3:    s_e  [128][257] (transposed embedding tile, 256 codes)
// ---------------------------------------------------------------------------
#define SMEM_FLOATS (TM * 129 + HDIM * 257)

__global__ __launch_bounds__(NT, 1)
void fused_kernel(const float* __restrict__ in,
                  const float* __restrict__ W1,
                  const float* __restrict__ b1,
                  const float* __restrict__ Wh,
                  const float* __restrict__ bh,
                  const float* __restrict__ E,
                  float* __restrict__ out,
                  int nrows) {
    extern __shared__ float sm[];
    float* s_h  = sm;                   // [64][129]
    float* s_in = sm + TM * 129;        // [64][65]
    float* s_w  = s_in + TM * 65;       // [128][128]
    float* s_e  = sm + TM * 129;        // [128][257], overlays s_in+s_w
    __shared__ int s_idx[TM];

    const int tid  = threadIdx.x;
    const int row0 = blockIdx.x * TM;

    // ---- load input tile (coalesced) + W1 ----
    for (int i = tid; i < TM * SDIM; i += NT) {
        int r = i >> 6, k = i & 63;
        s_in[r * 65 + k] = in[(size_t)(row0 + r) * SDIM + k];
    }
    for (int i = tid; i < SDIM * HDIM; i += NT) s_w[i] = W1[i];
    __syncthreads();

    const int rg = tid >> 4, cg = tid & 15;   // 16x16 thread grid, 4x8 micro-tile
    float acc[4][8];

    // ---- Phase 1: h1 = relu(in @ W1 + b1) ----
    {
#pragma unroll
        for (int j = 0; j < 8; j++) {
            float bb = b1[cg + 16 * j];
#pragma unroll
            for (int i = 0; i < 4; i++) acc[i][j] = bb;
        }
#pragma unroll 4
        for (int k = 0; k < SDIM; k++) {
            float a[4], b[8];
#pragma unroll
            for (int i = 0; i < 4; i++) a[i] = s_in[(rg + 16 * i) * 65 + k];
#pragma unroll
            for (int j = 0; j < 8; j++) b[j] = s_w[k * HDIM + cg + 16 * j];
#pragma unroll
            for (int i = 0; i < 4; i++)
#pragma unroll
                for (int j = 0; j < 8; j++) acc[i][j] = fmaf(a[i], b[j], acc[i][j]);
        }
    }
    __syncthreads();  // all reads of s_in/s_w done
#pragma unroll
    for (int i = 0; i < 4; i++)
#pragma unroll
        for (int j = 0; j < 8; j++)
            s_h[(rg + 16 * i) * 129 + cg + 16 * j] = fmaxf(acc[i][j], 0.f);
    for (int i = tid; i < HDIM * HDIM; i += NT) s_w[i] = Wh[i];
    __syncthreads();

    // ---- Phase 2: x = relu(h1 @ Wh + bh) ----
    {
#pragma unroll
        for (int j = 0; j < 8; j++) {
            float bb = bh[cg + 16 * j];
#pragma unroll
            for (int i = 0; i < 4; i++) acc[i][j] = bb;
        }
#pragma unroll 4
        for (int k = 0; k < HDIM; k++) {
            float a[4], b[8];
#pragma unroll
            for (int i = 0; i < 4; i++) a[i] = s_h[(rg + 16 * i) * 129 + k];
#pragma unroll
            for (int j = 0; j < 8; j++) b[j] = s_w[k * HDIM + cg + 16 * j];
#pragma unroll
            for (int i = 0; i < 4; i++)
#pragma unroll
                for (int j = 0; j < 8; j++) acc[i][j] = fmaf(a[i], b[j], acc[i][j]);
        }
    }
    __syncthreads();  // reads of s_h (old) and s_w complete
#pragma unroll
    for (int i = 0; i < 4; i++)
#pragma unroll
        for (int j = 0; j < 8; j++)
            s_h[(rg + 16 * i) * 129 + cg + 16 * j] = fmaxf(acc[i][j], 0.f);

    // ---- Phase 3: VQ argmin over 512 codes, 2 tiles of 256 ----
    const int warp = tid >> 5, lane = tid & 31;  // 8 warps x 32 lanes; 8x8 micro-tile
    float best[8];
    int   bidx[8];
#pragma unroll
    for (int i = 0; i < 8; i++) { best[i] = 3.4e38f; bidx[i] = 0x7fffffff; }

    for (int tile = 0; tile < 2; tile++) {
        const int cb = tile * 256;
        __syncthreads();  // prior s_e / s_h readers done before overwrite
        // transposed load: s_e[k][code]; gmem coalesced, smem stride 257 (odd)
        for (int i = tid; i < 256 * HDIM; i += NT) {
            int code = i >> 7, k = i & 127;
            s_e[k * 257 + code] = E[(size_t)(cb + code) * HDIM + k];
        }
        __syncthreads();

        float sc[8][8];
#pragma unroll
        for (int i = 0; i < 8; i++)
#pragma unroll
            for (int j = 0; j < 8; j++) sc[i][j] = 0.f;

#pragma unroll 2
        for (int k = 0; k < HDIM; k++) {
            float a[8], b[8];
#pragma unroll
            for (int i = 0; i < 8; i++) a[i] = s_h[(warp * 8 + i) * 129 + k];  // broadcast
#pragma unroll
            for (int j = 0; j < 8; j++) b[j] = s_e[k * 257 + lane + 32 * j];   // conflict-free
#pragma unroll
            for (int i = 0; i < 8; i++)
#pragma unroll
                for (int j = 0; j < 8; j++) sc[i][j] = fmaf(a[i], b[j], sc[i][j]);
        }
#pragma unroll
        for (int j = 0; j < 8; j++) {
            int c = cb + lane + 32 * j;
            float en = g_enorm[c];
#pragma unroll
            for (int i = 0; i < 8; i++) {
                float s = fmaf(-2.f, sc[i][j], en);  // ||e||^2 - 2 x.e
                if (s < best[i] || (s == best[i] && c < bidx[i])) { best[i] = s; bidx[i] = c; }
            }
        }
    }

    // warp-local argmin reduce (rows of a warp live entirely in that warp)
#pragma unroll
    for (int i = 0; i < 8; i++) {
        float bv_ = best[i]; int bi = bidx[i];
#pragma unroll
        for (int off = 16; off; off >>= 1) {
            float ob = __shfl_down_sync(0xffffffffu, bv_, off);
            int   oi = __shfl_down_sync(0xffffffffu, bi, off);
            if (ob < bv_ || (ob == bv_ && oi < bi)) { bv_ = ob; bi = oi; }
        }
        if (lane == 0) s_idx[warp * 8 + i] = bi;
    }
    __syncthreads();

    // ---- gather outputs: actions_prob [N,8] then value [N] ----
    float* outa = out;
    float* outv = out + (size_t)nrows * ADIM;
    for (int i = tid; i < TM * ADIM; i += NT) {
        int r = i >> 3, a = i & 7;
        outa[(size_t)(row0 + r) * ADIM + a] = g_probs[s_idx[r] * ADIM + a];
    }
    for (int i = tid; i < TM; i += NT)
        outv[row0 + i] = g_value[s_idx[i]];
}

// ---------------------------------------------------------------------------
extern "C" void kernel_launch(void* const* d_in, const int* in_sizes, int n_in,
                              void* d_out, int out_size) {
    const float* in = (const float*)d_in[0];
    const float* W1 = (const float*)d_in[1];
    const float* b1 = (const float*)d_in[2];
    const float* Wh = (const float*)d_in[3];
    const float* bh = (const float*)d_in[4];
    const float* E  = (const float*)d_in[5];
    const float* Wa = (const float*)d_in[6];
    const float* ba = (const float*)d_in[7];
    const float* Wv = (const float*)d_in[8];
    const float* bv = (const float*)d_in[9];
    float* out = (float*)d_out;

    const int nrows = in_sizes[0] / SDIM;  // 131072

    head_kernel<<<(KC + 255) / 256, 256>>>(E, Wa, ba, Wv, bv);

    const int smem_bytes = SMEM_FLOATS * (int)sizeof(float);  // 164,608 B
    cudaFuncSetAttribute(fused_kernel,
                         cudaFuncAttributeMaxDynamicSharedMemorySize, smem_bytes);
    fused_kernel<<<nrows / TM, NT, smem_bytes>>>(in, W1, b1, Wh, bh, E, out, nrows);
}

// round 2
// speedup vs baseline: 1.4448x; 1.4448x over previous
#include <cuda_runtime.h>
#include <math.h>

#define SDIM 64
#define HDIM 128
#define KC   512
#define ADIM 8
#define TM   128
#define NT   512

__device__ float g_probs[KC * ADIM];
__device__ float g_value[KC];
__device__ float g_enorm[KC];

// packed fp32x2 FMA (Blackwell sm_103a): d = a*b + c elementwise on 2 floats
__device__ __forceinline__ float2 ffma2(float2 a, float2 b, float2 c) {
    float2 d;
    asm("fma.rn.f32x2 %0, %1, %2, %3;"
        : "=l"(reinterpret_cast<unsigned long long&>(d))
        : "l"(reinterpret_cast<unsigned long long&>(a)),
          "l"(reinterpret_cast<unsigned long long&>(b)),
          "l"(reinterpret_cast<unsigned long long&>(c)));
    return d;
}

// ---------------------------------------------------------------------------
// Kernel 0: per-codebook-entry head precompute (quantize == E[idx] exactly).
// ---------------------------------------------------------------------------
__global__ void head_kernel(const float* __restrict__ E,
                            const float* __restrict__ Wa,
                            const float* __restrict__ ba,
                            const float* __restrict__ Wv,
                            const float* __restrict__ bv) {
    int c = blockIdx.x * blockDim.x + threadIdx.x;
    if (c >= KC) return;
    float logit[ADIM];
#pragma unroll
    for (int a = 0; a < ADIM; a++) logit[a] = ba[a];
    float en = 0.f, val = bv[0];
    for (int k = 0; k < HDIM; k++) {
        float ev = E[c * HDIM + k];
        en  = fmaf(ev, ev, en);
        val = fmaf(ev, Wv[k], val);
#pragma unroll
        for (int a = 0; a < ADIM; a++)
            logit[a] = fmaf(ev, Wa[k * ADIM + a], logit[a]);
    }
    float m = logit[0];
#pragma unroll
    for (int a = 1; a < ADIM; a++) m = fmaxf(m, logit[a]);
    float s = 0.f;
#pragma unroll
    for (int a = 0; a < ADIM; a++) { logit[a] = expf(logit[a] - m); s += logit[a]; }
    float inv = 1.f / s;
#pragma unroll
    for (int a = 0; a < ADIM; a++) g_probs[c * ADIM + a] = logit[a] * inv;
    g_value[c] = val;
    g_enorm[c] = en;
}

// ---------------------------------------------------------------------------
// Fused kernel: 128 rows/block, 512 threads (16 warps).
//   Phase 1: h = relu(in @ W1 + b1)      [128,64]@[64,128]
//   Phase 2: x = relu(h @ Wh + bh)       [128,128]@[128,128]
//   Phase 3: argmin_k (||e_k||^2 - 2 x.e_k), 2 tiles of 256 codes
// All GEMM inner loops use packed fp32x2 FMA over column/code pairs.
// smem (198,144 B): s_h[128][129]; overlay { s_in[128][65]+s_w[128][128] }
//                   vs { s_e[128][258] (transposed code tile, pair-aligned) }
// ---------------------------------------------------------------------------
#define SMEM_FLOATS (TM * 129 + HDIM * 258)

__global__ __launch_bounds__(NT, 1)
void fused_kernel(const float* __restrict__ in,
                  const float* __restrict__ W1,
                  const float* __restrict__ b1,
                  const float* __restrict__ Wh,
                  const float* __restrict__ bh,
                  const float* __restrict__ E,
                  float* __restrict__ out,
                  int nrows) {
    extern __shared__ float sm[];
    float* s_h  = sm;                    // [128][129]
    float* s_in = sm + TM * 129;         // [128][65]
    float* s_w  = s_in + TM * 65;        // [128][128]
    float* s_e  = sm + TM * 129;         // [128][258] overlays s_in+s_w
    __shared__ int s_idx[TM];

    const int tid  = threadIdx.x;
    const int row0 = blockIdx.x * TM;

    // ---- load input tile + W1 ----
    for (int i = tid; i < TM * SDIM; i += NT) {
        int r = i >> 6, k = i & 63;
        s_in[r * 65 + k] = in[(size_t)(row0 + r) * SDIM + k];
    }
    for (int i = tid; i < SDIM * HDIM; i += NT) s_w[i] = W1[i];
    __syncthreads();

    // thread grid 32x16: rows rg+32i (i<4), col-pairs 2*cg+32*jp (jp<4)
    const int rg = tid >> 4, cg = tid & 15;
    float2 acc[4][4];

    // ---- Phase 1 ----
    {
#pragma unroll
        for (int jp = 0; jp < 4; jp++) {
            float2 bb = *(const float2*)&b1[2 * cg + 32 * jp];
#pragma unroll
            for (int i = 0; i < 4; i++) acc[i][jp] = bb;
        }
#pragma unroll 4
        for (int k = 0; k < SDIM; k++) {
            float2 b[4];
#pragma unroll
            for (int jp = 0; jp < 4; jp++)
                b[jp] = *(const float2*)&s_w[k * HDIM + 2 * cg + 32 * jp];
#pragma unroll
            for (int i = 0; i < 4; i++) {
                float av = s_in[(rg + 32 * i) * 65 + k];
                float2 a2 = make_float2(av, av);
#pragma unroll
                for (int jp = 0; jp < 4; jp++) acc[i][jp] = ffma2(a2, b[jp], acc[i][jp]);
            }
        }
    }
    __syncthreads();
#pragma unroll
    for (int i = 0; i < 4; i++)
#pragma unroll
        for (int jp = 0; jp < 4; jp++) {
            int r = rg + 32 * i, c = 2 * cg + 32 * jp;
            s_h[r * 129 + c]     = fmaxf(acc[i][jp].x, 0.f);
            s_h[r * 129 + c + 1] = fmaxf(acc[i][jp].y, 0.f);
        }
    for (int i = tid; i < HDIM * HDIM; i += NT) s_w[i] = Wh[i];
    __syncthreads();

    // ---- Phase 2 ----
    {
#pragma unroll
        for (int jp = 0; jp < 4; jp++) {
            float2 bb = *(const float2*)&bh[2 * cg + 32 * jp];
#pragma unroll
            for (int i = 0; i < 4; i++) acc[i][jp] = bb;
        }
#pragma unroll 2
        for (int k = 0; k < HDIM; k++) {
            float2 b[4];
#pragma unroll
            for (int jp = 0; jp < 4; jp++)
                b[jp] = *(const float2*)&s_w[k * HDIM + 2 * cg + 32 * jp];
#pragma unroll
            for (int i = 0; i < 4; i++) {
                float av = s_h[(rg + 32 * i) * 129 + k];
                float2 a2 = make_float2(av, av);
#pragma unroll
                for (int jp = 0; jp < 4; jp++) acc[i][jp] = ffma2(a2, b[jp], acc[i][jp]);
            }
        }
    }
    __syncthreads();  // all phase-2 reads of s_h done before overwrite
#pragma unroll
    for (int i = 0; i < 4; i++)
#pragma unroll
        for (int jp = 0; jp < 4; jp++) {
            int r = rg + 32 * i, c = 2 * cg + 32 * jp;
            s_h[r * 129 + c]     = fmaxf(acc[i][jp].x, 0.f);
            s_h[r * 129 + c + 1] = fmaxf(acc[i][jp].y, 0.f);
        }

    // ---- Phase 3: VQ argmin, 2 tiles of 256 codes ----
    const int warp = tid >> 5, lane = tid & 31;   // 16 warps x 8 rows each
    float best[8];
    int   bidx[8];
#pragma unroll
    for (int i = 0; i < 8; i++) { best[i] = 3.4e38f; bidx[i] = 0x7fffffff; }

    for (int tile = 0; tile < 2; tile++) {
        const int cb = tile * 256;
        __syncthreads();  // previous s_e / s_h consumers done
        // transposed load: s_e[k][code], pair-aligned stride 258
        for (int i = tid; i < 256 * HDIM; i += NT) {
            int code = i >> 7, k = i & 127;
            s_e[k * 258 + code] = E[(size_t)(cb + code) * HDIM + k];
        }
        __syncthreads();

        float2 sc[8][4];
#pragma unroll
        for (int i = 0; i < 8; i++)
#pragma unroll
            for (int jp = 0; jp < 4; jp++) sc[i][jp] = make_float2(0.f, 0.f);

#pragma unroll 2
        for (int k = 0; k < HDIM; k++) {
            float2 b[4];
#pragma unroll
            for (int jp = 0; jp < 4; jp++)
                b[jp] = *(const float2*)&s_e[k * 258 + 2 * (lane + 32 * jp)];
#pragma unroll
            for (int i = 0; i < 8; i++) {
                float av = s_h[(warp * 8 + i) * 129 + k];   // broadcast
                float2 a2 = make_float2(av, av);
#pragma unroll
                for (int jp = 0; jp < 4; jp++) sc[i][jp] = ffma2(a2, b[jp], sc[i][jp]);
            }
        }
#pragma unroll
        for (int jp = 0; jp < 4; jp++) {
            int c0 = cb + 2 * (lane + 32 * jp);
            float en0 = g_enorm[c0], en1 = g_enorm[c0 + 1];
#pragma unroll
            for (int i = 0; i < 8; i++) {
                float s0 = fmaf(-2.f, sc[i][jp].x, en0);
                float s1 = fmaf(-2.f, sc[i][jp].y, en1);
                if (s0 < best[i] || (s0 == best[i] && c0 < bidx[i])) { best[i] = s0; bidx[i] = c0; }
                if (s1 < best[i] || (s1 == best[i] && c0 + 1 < bidx[i])) { best[i] = s1; bidx[i] = c0 + 1; }
            }
        }
    }

    // warp argmin reduce (each row owned by exactly one warp)
#pragma unroll
    for (int i = 0; i < 8; i++) {
        float bv_ = best[i]; int bi = bidx[i];
#pragma unroll
        for (int off = 16; off; off >>= 1) {
            float ob = __shfl_down_sync(0xffffffffu, bv_, off);
            int   oi = __shfl_down_sync(0xffffffffu, bi, off);
            if (ob < bv_ || (ob == bv_ && oi < bi)) { bv_ = ob; bi = oi; }
        }
        if (lane == 0) s_idx[warp * 8 + i] = bi;
    }
    __syncthreads();

    // ---- gather outputs ----
    float* outa = out;
    float* outv = out + (size_t)nrows * ADIM;
    for (int i = tid; i < TM * ADIM; i += NT) {
        int r = i >> 3, a = i & 7;
        outa[(size_t)(row0 + r) * ADIM + a] = g_probs[s_idx[r] * ADIM + a];
    }
    for (int i = tid; i < TM; i += NT)
        outv[row0 + i] = g_value[s_idx[i]];
}

// ---------------------------------------------------------------------------
extern "C" void kernel_launch(void* const* d_in, const int* in_sizes, int n_in,
                              void* d_out, int out_size) {
    const float* in = (const float*)d_in[0];
    const float* W1 = (const float*)d_in[1];
    const float* b1 = (const float*)d_in[2];
    const float* Wh = (const float*)d_in[3];
    const float* bh = (const float*)d_in[4];
    const float* E  = (const float*)d_in[5];
    const float* Wa = (const float*)d_in[6];
    const float* ba = (const float*)d_in[7];
    const float* Wv = (const float*)d_in[8];
    const float* bv = (const float*)d_in[9];
    float* out = (float*)d_out;

    const int nrows = in_sizes[0] / SDIM;  // 131072

    head_kernel<<<(KC + 255) / 256, 256>>>(E, Wa, ba, Wv, bv);

    const int smem_bytes = SMEM_FLOATS * (int)sizeof(float);  // 198,144 B
    cudaFuncSetAttribute(fused_kernel,
                         cudaFuncAttributeMaxDynamicSharedMemorySize, smem_bytes);
    fused_kernel<<<nrows / TM, NT, smem_bytes>>>(in, W1, b1, Wh, bh, E, out, nrows);
}

// round 3
// speedup vs baseline: 1.5600x; 1.0798x over previous
#include <cuda_runtime.h>
#include <math.h>

#define SDIM 64
#define HDIM 128
#define KC   512
#define ADIM 8
#define TM   128
#define NT   512

#define SH_STRIDE 132   // s_h row stride (16B aligned, 132%32=4)
#define SI_STRIDE 68    // s_in row stride
#define SE_STRIDE 260   // s_e row stride (16B aligned)

__device__ float g_probs[KC * ADIM];
__device__ float g_value[KC];
__device__ float g_enorm[KC];

// packed fp32x2 FMA (sm_103a FFMA2, rt_SMSP=2 -> 2x scalar FLOP rate)
__device__ __forceinline__ float2 ffma2(float2 a, float2 b, float2 c) {
    float2 d;
    asm("fma.rn.f32x2 %0, %1, %2, %3;"
        : "=l"(reinterpret_cast<unsigned long long&>(d))
        : "l"(reinterpret_cast<unsigned long long&>(a)),
          "l"(reinterpret_cast<unsigned long long&>(b)),
          "l"(reinterpret_cast<unsigned long long&>(c)));
    return d;
}

// ---------------------------------------------------------------------------
// Kernel 0: per-code head precompute (quantize == E[idx] exactly).
// ---------------------------------------------------------------------------
__global__ void head_kernel(const float* __restrict__ E,
                            const float* __restrict__ Wa,
                            const float* __restrict__ ba,
                            const float* __restrict__ Wv,
                            const float* __restrict__ bv) {
    int c = blockIdx.x * blockDim.x + threadIdx.x;
    if (c >= KC) return;
    float logit[ADIM];
#pragma unroll
    for (int a = 0; a < ADIM; a++) logit[a] = ba[a];
    float en = 0.f, val = bv[0];
    for (int k = 0; k < HDIM; k++) {
        float ev = E[c * HDIM + k];
        en  = fmaf(ev, ev, en);
        val = fmaf(ev, Wv[k], val);
#pragma unroll
        for (int a = 0; a < ADIM; a++)
            logit[a] = fmaf(ev, Wa[k * ADIM + a], logit[a]);
    }
    float m = logit[0];
#pragma unroll
    for (int a = 1; a < ADIM; a++) m = fmaxf(m, logit[a]);
    float s = 0.f;
#pragma unroll
    for (int a = 0; a < ADIM; a++) { logit[a] = expf(logit[a] - m); s += logit[a]; }
    float inv = 1.f / s;
#pragma unroll
    for (int a = 0; a < ADIM; a++) g_probs[c * ADIM + a] = logit[a] * inv;
    g_value[c] = val;
    g_enorm[c] = en;
}

// ---------------------------------------------------------------------------
// Fused kernel: 128 rows/block, 512 threads (16 warps, 8 rows/warp).
// All LDS vectorized to .128; k unrolled by 4 (one float4-a-broadcast / 4 k).
// smem 200,704 B: s_h[128][132]; overlay { s_in[128][68] + s_w[128][128] }
//                 vs { s_e[128][260] (transposed 256-code tile) }
// ---------------------------------------------------------------------------
#define SMEM_FLOATS (TM * SH_STRIDE + HDIM * SE_STRIDE)

__global__ __launch_bounds__(NT, 1)
void fused_kernel(const float* __restrict__ in,
                  const float* __restrict__ W1,
                  const float* __restrict__ b1,
                  const float* __restrict__ Wh,
                  const float* __restrict__ bh,
                  const float* __restrict__ E,
                  float* __restrict__ out,
                  int nrows) {
    extern __shared__ float sm[];
    float* s_h  = sm;                          // [128][132]
    float* s_e  = sm + TM * SH_STRIDE;         // [128][260]
    float* s_in = s_e;                         // [128][68]   (overlay)
    float* s_w  = s_e + TM * SI_STRIDE;        // [128][128]  (overlay)
    __shared__ int s_idx[TM];

    const int tid  = threadIdx.x;
    const int warp = tid >> 5, lane = tid & 31;
    const int rbase = warp * 8;                // 8 rows per warp
    const int row0 = blockIdx.x * TM;

    // ---- load input tile + W1 ----
    for (int i = tid; i < TM * SDIM; i += NT) {
        int r = i >> 6, k = i & 63;
        s_in[r * SI_STRIDE + k] = in[(size_t)(row0 + r) * SDIM + k];
    }
    for (int i = tid; i < SDIM * HDIM; i += NT) s_w[i] = W1[i];
    __syncthreads();

    float2 acc[8][2];   // 8 rows x cols [4*lane .. 4*lane+3]

    // ---- Phase 1: h = relu(in @ W1 + b1) ----
    {
        float4 bb = *(const float4*)&b1[4 * lane];
#pragma unroll
        for (int i = 0; i < 8; i++) {
            acc[i][0] = make_float2(bb.x, bb.y);
            acc[i][1] = make_float2(bb.z, bb.w);
        }
#pragma unroll 1
        for (int k4 = 0; k4 < SDIM; k4 += 4) {
            float a4[8][4];
#pragma unroll
            for (int i = 0; i < 8; i++)
                *(float4*)&a4[i][0] = *(const float4*)&s_in[(rbase + i) * SI_STRIDE + k4];
#pragma unroll
            for (int j = 0; j < 4; j++) {
                float4 b4 = *(const float4*)&s_w[(k4 + j) * HDIM + 4 * lane];
                float2 blo = make_float2(b4.x, b4.y), bhi = make_float2(b4.z, b4.w);
#pragma unroll
                for (int i = 0; i < 8; i++) {
                    float2 a2 = make_float2(a4[i][j], a4[i][j]);
                    acc[i][0] = ffma2(a2, blo, acc[i][0]);
                    acc[i][1] = ffma2(a2, bhi, acc[i][1]);
                }
            }
        }
    }
    // store h (s_h distinct from s_in/s_w: no hazard yet)
#pragma unroll
    for (int i = 0; i < 8; i++) {
        float4 v = make_float4(fmaxf(acc[i][0].x, 0.f), fmaxf(acc[i][0].y, 0.f),
                               fmaxf(acc[i][1].x, 0.f), fmaxf(acc[i][1].y, 0.f));
        *(float4*)&s_h[(rbase + i) * SH_STRIDE + 4 * lane] = v;
    }
    __syncthreads();   // all P1 reads of s_w done
    for (int i = tid; i < HDIM * HDIM; i += NT) s_w[i] = Wh[i];
    __syncthreads();

    // ---- Phase 2: x = relu(h @ Wh + bh) ----
    {
        float4 bb = *(const float4*)&bh[4 * lane];
#pragma unroll
        for (int i = 0; i < 8; i++) {
            acc[i][0] = make_float2(bb.x, bb.y);
            acc[i][1] = make_float2(bb.z, bb.w);
        }
#pragma unroll 1
        for (int k4 = 0; k4 < HDIM; k4 += 4) {
            float a4[8][4];
#pragma unroll
            for (int i = 0; i < 8; i++)
                *(float4*)&a4[i][0] = *(const float4*)&s_h[(rbase + i) * SH_STRIDE + k4];
#pragma unroll
            for (int j = 0; j < 4; j++) {
                float4 b4 = *(const float4*)&s_w[(k4 + j) * HDIM + 4 * lane];
                float2 blo = make_float2(b4.x, b4.y), bhi = make_float2(b4.z, b4.w);
#pragma unroll
                for (int i = 0; i < 8; i++) {
                    float2 a2 = make_float2(a4[i][j], a4[i][j]);
                    acc[i][0] = ffma2(a2, blo, acc[i][0]);
                    acc[i][1] = ffma2(a2, bhi, acc[i][1]);
                }
            }
        }
    }
    // warp-private rows: only intra-warp read->write hazard on s_h
    __syncwarp();
#pragma unroll
    for (int i = 0; i < 8; i++) {
        float4 v = make_float4(fmaxf(acc[i][0].x, 0.f), fmaxf(acc[i][0].y, 0.f),
                               fmaxf(acc[i][1].x, 0.f), fmaxf(acc[i][1].y, 0.f));
        *(float4*)&s_h[(rbase + i) * SH_STRIDE + 4 * lane] = v;
    }

    // ---- Phase 3: VQ argmin over 512 codes, 2 tiles of 256 ----
    float best[8];
    int   bidx[8];
#pragma unroll
    for (int i = 0; i < 8; i++) { best[i] = 3.4e38f; bidx[i] = 0x7fffffff; }

    for (int tile = 0; tile < 2; tile++) {
        const int cb = tile * 256;
        __syncthreads();   // prior s_w/s_e consumers done before overwrite
        // transposed tile: s_e[k][code]
        for (int i = tid; i < 256 * HDIM; i += NT) {
            int code = i >> 7, k = i & 127;
            s_e[k * SE_STRIDE + code] = E[(size_t)(cb + code) * HDIM + k];
        }
        __syncthreads();

        // lane covers codes {4*lane..+3} and {128+4*lane..+3}
        float2 sc[8][4];
#pragma unroll
        for (int i = 0; i < 8; i++)
#pragma unroll
            for (int jp = 0; jp < 4; jp++) sc[i][jp] = make_float2(0.f, 0.f);

#pragma unroll 1
        for (int k4 = 0; k4 < HDIM; k4 += 4) {
            float a4[8][4];
#pragma unroll
            for (int i = 0; i < 8; i++)
                *(float4*)&a4[i][0] = *(const float4*)&s_h[(rbase + i) * SH_STRIDE + k4];
#pragma unroll
            for (int j = 0; j < 4; j++) {
                const float* er = &s_e[(k4 + j) * SE_STRIDE];
                float4 e0 = *(const float4*)&er[4 * lane];
                float4 e1 = *(const float4*)&er[4 * lane + 128];
                float2 p0 = make_float2(e0.x, e0.y), p1 = make_float2(e0.z, e0.w);
                float2 p2 = make_float2(e1.x, e1.y), p3 = make_float2(e1.z, e1.w);
#pragma unroll
                for (int i = 0; i < 8; i++) {
                    float2 a2 = make_float2(a4[i][j], a4[i][j]);
                    sc[i][0] = ffma2(a2, p0, sc[i][0]);
                    sc[i][1] = ffma2(a2, p1, sc[i][1]);
                    sc[i][2] = ffma2(a2, p2, sc[i][2]);
                    sc[i][3] = ffma2(a2, p3, sc[i][3]);
                }
            }
        }
        // fold: codes ascending per lane for correct lowest-index tie-break
#pragma unroll
        for (int jp = 0; jp < 4; jp++) {
            int c0 = cb + ((jp < 2) ? (4 * lane + 2 * jp)
                                    : (128 + 4 * lane + 2 * (jp - 2)));
            float en0 = g_enorm[c0], en1 = g_enorm[c0 + 1];
#pragma unroll
            for (int i = 0; i < 8; i++) {
                float s0 = fmaf(-2.f, sc[i][jp].x, en0);
                float s1 = fmaf(-2.f, sc[i][jp].y, en1);
                if (s0 < best[i] || (s0 == best[i] && c0 < bidx[i]))       { best[i] = s0; bidx[i] = c0; }
                if (s1 < best[i] || (s1 == best[i] && c0 + 1 < bidx[i]))   { best[i] = s1; bidx[i] = c0 + 1; }
            }
        }
    }

    // warp argmin reduce (rows owned by exactly one warp)
#pragma unroll
    for (int i = 0; i < 8; i++) {
        float bv_ = best[i]; int bi = bidx[i];
#pragma unroll
        for (int off = 16; off; off >>= 1) {
            float ob = __shfl_down_sync(0xffffffffu, bv_, off);
            int   oi = __shfl_down_sync(0xffffffffu, bi, off);
            if (ob < bv_ || (ob == bv_ && oi < bi)) { bv_ = ob; bi = oi; }
        }
        if (lane == 0) s_idx[rbase + i] = bi;
    }
    __syncthreads();

    // ---- gather outputs ----
    float* outa = out;
    float* outv = out + (size_t)nrows * ADIM;
    for (int i = tid; i < TM * ADIM; i += NT) {
        int r = i >> 3, a = i & 7;
        outa[(size_t)(row0 + r) * ADIM + a] = g_probs[s_idx[r] * ADIM + a];
    }
    for (int i = tid; i < TM; i += NT)
        outv[row0 + i] = g_value[s_idx[i]];
}

// ---------------------------------------------------------------------------
extern "C" void kernel_launch(void* const* d_in, const int* in_sizes, int n_in,
                              void* d_out, int out_size) {
    const float* in = (const float*)d_in[0];
    const float* W1 = (const float*)d_in[1];
    const float* b1 = (const float*)d_in[2];
    const float* Wh = (const float*)d_in[3];
    const float* bh = (const float*)d_in[4];
    const float* E  = (const float*)d_in[5];
    const float* Wa = (const float*)d_in[6];
    const float* ba = (const float*)d_in[7];
    const float* Wv = (const float*)d_in[8];
    const float* bv = (const float*)d_in[9];
    float* out = (float*)d_out;

    const int nrows = in_sizes[0] / SDIM;  // 131072

    head_kernel<<<(KC + 255) / 256, 256>>>(E, Wa, ba, Wv, bv);

    const int smem_bytes = SMEM_FLOATS * (int)sizeof(float);  // 200,704 B
    cudaFuncSetAttribute(fused_kernel,
                         cudaFuncAttributeMaxDynamicSharedMemorySize, smem_bytes);
    fused_kernel<<<nrows / TM, NT, smem_bytes>>>(in, W1, b1, Wh, bh, E, out, nrows);
}